// round 12
// baseline (speedup 1.0000x reference)
#include <cuda_runtime.h>
#include <cuda_fp16.h>
#include <cstdint>

// ---------------------------------------------------------------------------
// Problem constants
// ---------------------------------------------------------------------------
static constexpr int VOCAB = 32000;
static constexpr int DIMS  = 1024;
static constexpr int BB    = 2;
static constexpr int LL    = 2048;
static constexpr int MROWS = BB * LL;          // 4096
static constexpr int SEGS  = 128;              // cummean scan segments
static constexpr int SEGL  = LL / SEGS;        // 16
static constexpr int DCH   = 2;                // dim chunks per (b,seg) scan block

// Scratch (static device globals: allocation-free)
// cummean commutes with the W_V projection (both linear): scan first, then GEMMs.
__device__ __half g_eavg[MROWS * DIMS];        // fp16 cummean(e)   (A of GEMM1)
__device__ __half g_avg [MROWS * DIMS];        // fp16 avg = cummean(e)@W_V^T (A of GEMM2)
__device__ __half g_wv  [DIMS * DIMS];         // fp16 W_V
__device__ __half g_wo  [VOCAB * DIMS];        // fp16 W_out
__device__ float  g_seg [BB * SEGS * DIMS];    // segment sums for scan
__device__ int    g_is64;

// ---------------------------------------------------------------------------
// PTX helpers (base sm_100-compatible: cp.async + ldmatrix + mma.sync fp16)
// ---------------------------------------------------------------------------
__device__ __forceinline__ uint32_t smem_u32(const void* p) {
    uint32_t a;
    asm("{ .reg .u64 t; cvta.to.shared.u64 t, %1; cvt.u32.u64 %0, t; }" : "=r"(a) : "l"(p));
    return a;
}

#define CP_ASYNC16(dst, src) \
    asm volatile("cp.async.cg.shared.global [%0], [%1], 16;" :: "r"(dst), "l"(src) : "memory")
#define CP_COMMIT() asm volatile("cp.async.commit_group;" ::: "memory")
#define CP_WAIT1()  asm volatile("cp.async.wait_group 1;" ::: "memory")

__device__ __forceinline__ void ldsm_x4(uint32_t* r, uint32_t addr) {
    asm volatile("ldmatrix.sync.aligned.m8n8.x4.shared.b16 {%0,%1,%2,%3}, [%4];"
                 : "=r"(r[0]), "=r"(r[1]), "=r"(r[2]), "=r"(r[3]) : "r"(addr));
}

// fp16 MMA, fp32 accumulate: D[16,8] += A[16,16] * B[16,8] (B col-major = N,K row)
__device__ __forceinline__ void mma_f16(float* c, const uint32_t* a,
                                        uint32_t b0, uint32_t b1) {
    asm volatile(
        "mma.sync.aligned.m16n8k16.row.col.f32.f16.f16.f32 "
        "{%0,%1,%2,%3}, {%4,%5,%6,%7}, {%8,%9}, {%0,%1,%2,%3};"
        : "+f"(c[0]), "+f"(c[1]), "+f"(c[2]), "+f"(c[3])
        : "r"(a[0]), "r"(a[1]), "r"(a[2]), "r"(a[3]), "r"(b0), "r"(b1));
}

// ---------------------------------------------------------------------------
// GEMM: C[M,N] = A[M,K] * B[N,K]^T (+bias), fp16 mma.sync, fp32 accumulate.
// CTA tile 128(M) x 128(N) x 64(K); 4 warps (2x2) of 64x64; 3-stage cp.async.
// TWO CTAs per SM; grid x->M so co-resident CTAs share the B slice (L2-hot).
// Output dtype chosen at COMPILE time (OUT_HALF template).
// ---------------------------------------------------------------------------
static constexpr int MT = 128;
static constexpr int NT = 128;
static constexpr int KC = 64;                      // halves of K per chunk (128B/row)
static constexpr int STAGES = 3;
static constexpr int THREADS = 128;
static constexpr int ROWB = 144;                   // padded row stride in bytes
static constexpr int A_BYTES = MT * ROWB;          // 18432
static constexpr int B_BYTES = NT * ROWB;          // 18432
static constexpr int BUF     = A_BYTES + B_BYTES;  // 36864
static constexpr int SMEM_TOTAL = STAGES * BUF;    // 110592 (x2 CTAs = 221184 < 227KB)

__device__ __forceinline__ void load_chunk(uint32_t bufb,
                                           const __half* __restrict__ A,
                                           const __half* __restrict__ Bm,
                                           int mbase, int nbase, int K, int kc, int tid) {
    const int kofs = kc * KC;
#pragma unroll
    for (int i = 0; i < 8; i++) {                  // A: 128 rows x 8 segs / 128 thr
        int j = tid + (i << 7);
        int r = j >> 3, s = j & 7;
        const __half* src = A + (size_t)(mbase + r) * K + kofs + s * 8;
        CP_ASYNC16(bufb + (uint32_t)(r * ROWB + s * 16), src);
    }
#pragma unroll
    for (int i = 0; i < 8; i++) {                  // B: 128 rows x 8 segs / 128 thr
        int j = tid + (i << 7);
        int r = j >> 3, s = j & 7;
        const __half* src = Bm + (size_t)(nbase + r) * K + kofs + s * 8;
        CP_ASYNC16(bufb + (uint32_t)A_BYTES + (uint32_t)(r * ROWB + s * 16), src);
    }
}

// load fragments for one k16 step (4 A tiles m16k16, 4 B tiles n16k16)
__device__ __forceinline__ void load_frags(uint32_t bufb, uint32_t a_lane, uint32_t b_lane,
                                           int ks, uint32_t a[4][4], uint32_t b[4][4]) {
    const uint32_t boff = (uint32_t)(ks * 32);     // 16 halves = 32B per k16 step
#pragma unroll
    for (int mt = 0; mt < 4; mt++)
        ldsm_x4(a[mt], bufb + a_lane + (uint32_t)(mt * 16 * ROWB) + boff);
#pragma unroll
    for (int np = 0; np < 4; np++)
        ldsm_x4(b[np], bufb + b_lane + (uint32_t)(np * 16 * ROWB) + boff);
}

template <bool OUT_HALF>
__global__ void __launch_bounds__(THREADS, 2)
gemm_f16_mma(const __half* __restrict__ A, const __half* __restrict__ Bm,
             const float* __restrict__ bias, float* __restrict__ C,
             __half* __restrict__ Ch, int M, int N, int K) {
    extern __shared__ __align__(16) char smem[];
    const uint32_t sb = smem_u32(smem);
    const int tid = threadIdx.x;
    const int wid = tid >> 5;
    const int l   = tid & 31;
    const int wm  = wid >> 1;          // 0..1  (M warp row, 64 rows each)
    const int wn  = wid & 1;           // 0..1  (N warp col, 64 cols each)
    const int mbase = blockIdx.x * MT; // bx -> M: co-resident CTAs share B slice
    const int nbase = blockIdx.y * NT;

    const int      lrow = (l & 7) + ((l >> 3) & 1) * 8;
    const uint32_t lhi  = (uint32_t)((l >> 4) * 16);
    const uint32_t a_lane = (uint32_t)((wm * 64 + lrow) * ROWB) + lhi;
    const uint32_t b_lane = (uint32_t)A_BYTES + (uint32_t)((wn * 64 + lrow) * ROWB) + lhi;

    float c[4][8][4];
#pragma unroll
    for (int mt = 0; mt < 4; mt++)
#pragma unroll
        for (int nt = 0; nt < 8; nt++)
#pragma unroll
            for (int q = 0; q < 4; q++) c[mt][nt][q] = 0.0f;

    const int nch = K / KC;            // 16 for K=1024

    load_chunk(sb, A, Bm, mbase, nbase, K, 0, tid);
    CP_COMMIT();
    load_chunk(sb + BUF, A, Bm, mbase, nbase, K, 1, tid);
    CP_COMMIT();

    uint32_t afr[2][4][4], bfr[2][4][4];
    uint32_t slot = 0;
    for (int kc = 0; kc < nch; kc++) {
        CP_WAIT1();
        __syncthreads();
        const uint32_t bufb = sb + slot * BUF;
        if (kc + 2 < nch) {
            uint32_t ws = slot + 2; if (ws >= STAGES) ws -= STAGES;
            load_chunk(sb + ws * BUF, A, Bm, mbase, nbase, K, kc + 2, tid);
        }
        CP_COMMIT();

        load_frags(bufb, a_lane, b_lane, 0, afr[0], bfr[0]);
#pragma unroll
        for (int ks = 0; ks < 4; ks++) {           // 4 x k16 = K chunk of 64
            const int cur = ks & 1;
            if (ks < 3)
                load_frags(bufb, a_lane, b_lane, ks + 1, afr[cur ^ 1], bfr[cur ^ 1]);
#pragma unroll
            for (int mt = 0; mt < 4; mt++)
#pragma unroll
                for (int nt = 0; nt < 8; nt++) {
                    const int np = nt >> 1, od = nt & 1;
                    mma_f16(c[mt][nt], afr[cur][mt], bfr[cur][np][od], bfr[cur][np][2 + od]);
                }
        }
        slot++; if (slot >= STAGES) slot = 0;
    }

    // Epilogue: rows = mbase+wm*64+mt*16+{g,g+8}, cols = nbase+wn*64+nt*8+2t+{0,1}
    const int g = l >> 2, t = l & 3;
    const int row0 = mbase + wm * 64 + g;
    const int colb = nbase + wn * 64 + t * 2;
#pragma unroll
    for (int nt = 0; nt < 8; nt++) {
        float2 bv = make_float2(0.0f, 0.0f);
        if (bias) bv = *reinterpret_cast<const float2*>(bias + colb + nt * 8);
#pragma unroll
        for (int mt = 0; mt < 4; mt++) {
            const int r = row0 + mt * 16;
            float2 v0 = make_float2(c[mt][nt][0] + bv.x, c[mt][nt][1] + bv.y);
            float2 v1 = make_float2(c[mt][nt][2] + bv.x, c[mt][nt][3] + bv.y);
            if (OUT_HALF) {
                *reinterpret_cast<__half2*>(Ch + (size_t)r * N + colb + nt * 8)
                    = __floats2half2_rn(v0.x, v0.y);
                *reinterpret_cast<__half2*>(Ch + (size_t)(r + 8) * N + colb + nt * 8)
                    = __floats2half2_rn(v1.x, v1.y);
            } else {
                *reinterpret_cast<float2*>(C + (size_t)r * N + colb + nt * 8)       = v0;
                *reinterpret_cast<float2*>(C + (size_t)(r + 8) * N + colb + nt * 8) = v1;
            }
        }
    }
}

// ---------------------------------------------------------------------------
// Small kernels
// ---------------------------------------------------------------------------
__global__ void detect_kernel(const void* seq) {
    __shared__ int ok;
    if (threadIdx.x == 0) ok = 1;
    __syncthreads();
    const long long* p = (const long long*)seq;   // reads 16KB <= int32 buffer size
    for (int i = threadIdx.x; i < MROWS / 2; i += blockDim.x) {
        long long v = p[i];
        if (v < 0 || v >= VOCAB) ok = 0;
    }
    __syncthreads();
    if (threadIdx.x == 0) g_is64 = ok;
}

__device__ __forceinline__ long long get_tok(const void* seq, int idx) {
    if (g_is64) return ((const long long*)seq)[idx];
    return (long long)((const int*)seq)[idx];
}

// fp32 weights -> fp16 (round-to-nearest); 2 float4 per thread for MLP
__global__ void cvt_kernel(const float* __restrict__ src, __half* __restrict__ dst) {
    const size_t i0 = ((size_t)blockIdx.x * blockDim.x + threadIdx.x) * 2;
    float4 v0 = reinterpret_cast<const float4*>(src)[i0];
    float4 v1 = reinterpret_cast<const float4*>(src)[i0 + 1];
    __half2 h[4];
    h[0] = __floats2half2_rn(v0.x, v0.y);
    h[1] = __floats2half2_rn(v0.z, v0.w);
    h[2] = __floats2half2_rn(v1.x, v1.y);
    h[3] = __floats2half2_rn(v1.z, v1.w);
    reinterpret_cast<float4*>(dst)[i0 >> 1] = *reinterpret_cast<float4*>(h);
}

// --- fused gather + causal cumulative mean over EMBEDDINGS (scan-first) ----
// pass 1: per-(b,seg) sums of gathered embedding rows (fp32)
__global__ void segsum_emb(const void* __restrict__ seq, const float* __restrict__ emb,
                           float* __restrict__ S) {
    const int bs   = blockIdx.x >> 1;             // (b*SEGS+seg)
    const int b    = bs / SEGS;
    const int seg  = bs % SEGS;
    const int d    = (blockIdx.x & 1) * (DIMS / DCH) + threadIdx.x * 2;
    const int lbase = b * LL + seg * SEGL;
    float2 acc = make_float2(0.f, 0.f);
#pragma unroll
    for (int lq = 0; lq < SEGL; lq++) {
        const long long tok = get_tok(seq, lbase + lq);
        float2 v = *reinterpret_cast<const float2*>(emb + (size_t)tok * DIMS + d);
        acc.x += v.x; acc.y += v.y;
    }
    *reinterpret_cast<float2*>(S + (size_t)bs * DIMS + d) = acc;
}

// pass 2: prefix of segment sums (4-way MLP) + in-segment running mean -> fp16
__global__ void cummean_emb(const void* __restrict__ seq, const float* __restrict__ emb,
                            const float* __restrict__ S, __half* __restrict__ eavg) {
    const int bs   = blockIdx.x >> 1;
    const int b    = bs / SEGS;
    const int seg  = bs % SEGS;
    const int d    = (blockIdx.x & 1) * (DIMS / DCH) + threadIdx.x * 2;
    float2 a0 = make_float2(0.f, 0.f);
    float2 a1 = a0, a2 = a0, a3 = a0;
    const float* Sp = S + (size_t)b * SEGS * DIMS + d;
    int j = 0;
    for (; j + 4 <= seg; j += 4) {
        float2 s0 = *reinterpret_cast<const float2*>(Sp + (size_t)(j + 0) * DIMS);
        float2 s1 = *reinterpret_cast<const float2*>(Sp + (size_t)(j + 1) * DIMS);
        float2 s2 = *reinterpret_cast<const float2*>(Sp + (size_t)(j + 2) * DIMS);
        float2 s3 = *reinterpret_cast<const float2*>(Sp + (size_t)(j + 3) * DIMS);
        a0.x += s0.x; a0.y += s0.y;
        a1.x += s1.x; a1.y += s1.y;
        a2.x += s2.x; a2.y += s2.y;
        a3.x += s3.x; a3.y += s3.y;
    }
    for (; j < seg; j++) {
        float2 s0 = *reinterpret_cast<const float2*>(Sp + (size_t)j * DIMS);
        a0.x += s0.x; a0.y += s0.y;
    }
    float2 acc;
    acc.x = (a0.x + a1.x) + (a2.x + a3.x);
    acc.y = (a0.y + a1.y) + (a2.y + a3.y);

    const int lbase = b * LL + seg * SEGL;
    __half* ap = eavg + (size_t)lbase * DIMS + d;
#pragma unroll
    for (int lq = 0; lq < SEGL; lq++) {
        const long long tok = get_tok(seq, lbase + lq);
        float2 v = *reinterpret_cast<const float2*>(emb + (size_t)tok * DIMS + d);
        acc.x += v.x; acc.y += v.y;
        const float inv = 1.0f / (float)(seg * SEGL + lq + 1);
        *reinterpret_cast<__half2*>(ap + (size_t)lq * DIMS)
            = __floats2half2_rn(acc.x * inv, acc.y * inv);
    }
}

// ---------------------------------------------------------------------------
// Launch: two-stream fork/join (capturable pattern: event record + stream wait)
// Stream W (weights): cvt_wv -> evWv ; cvt_wo -> evWo
// Stream 0 (default): detect -> segsum -> cummean -> [wait evWv] GEMM1
//                     -> [wait evWo] GEMM2
// Streams/events are created fresh per call; kernel_launch only executes for
// the correctness run + the capture run (replays execute the graph), so no
// unbounded resource growth. No device memory is allocated.
// ---------------------------------------------------------------------------
extern "C" void kernel_launch(void* const* d_in, const int* in_sizes, int n_in,
                              void* d_out, int out_size) {
    const void*  seq = d_in[0];
    const float* emb = (const float*)d_in[1];
    const float* WV  = (const float*)d_in[2];
    const float* WO  = (const float*)d_in[3];
    const float* bo  = (const float*)d_in[4];
    float* out = (float*)d_out;

    cudaFuncSetAttribute(gemm_f16_mma<false>,
                         cudaFuncAttributeMaxDynamicSharedMemorySize, SMEM_TOTAL);
    cudaFuncSetAttribute(gemm_f16_mma<true>,
                         cudaFuncAttributeMaxDynamicSharedMemorySize, SMEM_TOTAL);

    __half *gea, *ga, *gwv, *gwo;
    float *gs;
    cudaGetSymbolAddress((void**)&gea, g_eavg);
    cudaGetSymbolAddress((void**)&ga,  g_avg);
    cudaGetSymbolAddress((void**)&gwv, g_wv);
    cudaGetSymbolAddress((void**)&gwo, g_wo);
    cudaGetSymbolAddress((void**)&gs,  g_seg);

    cudaStream_t sW;
    cudaEvent_t evFork, evWv, evWo;
    cudaStreamCreateWithFlags(&sW, cudaStreamNonBlocking);
    cudaEventCreateWithFlags(&evFork, cudaEventDisableTiming);
    cudaEventCreateWithFlags(&evWv,   cudaEventDisableTiming);
    cudaEventCreateWithFlags(&evWo,   cudaEventDisableTiming);

    // fork: weight converts on sW
    cudaEventRecord(evFork, 0);
    cudaStreamWaitEvent(sW, evFork, 0);
    cvt_kernel<<<(DIMS * DIMS) / 8 / 256, 256, 0, sW>>>(WV, gwv);
    cudaEventRecord(evWv, sW);
    cvt_kernel<<<(VOCAB * DIMS) / 8 / 256, 256, 0, sW>>>(WO, gwo);
    cudaEventRecord(evWo, sW);

    // main chain: token detect + scan-first cummean(e)
    detect_kernel<<<1, 256>>>(seq);
    segsum_emb<<<BB * SEGS * DCH, 256>>>(seq, emb, gs);
    cummean_emb<<<BB * SEGS * DCH, 256>>>(seq, emb, gs, gea);

    // GEMM1 needs cvt_wv: avg = cummean(e) @ W_V^T, fp16 output
    cudaStreamWaitEvent(0, evWv, 0);
    gemm_f16_mma<true><<<dim3(MROWS / MT, DIMS / NT), THREADS, SMEM_TOTAL>>>(
        gea, gwv, nullptr, nullptr, ga, MROWS, DIMS, DIMS);

    // GEMM2 needs cvt_wo: out = avg @ W_out^T + b, fp32 output
    cudaStreamWaitEvent(0, evWo, 0);
    gemm_f16_mma<false><<<dim3(MROWS / MT, VOCAB / NT), THREADS, SMEM_TOTAL>>>(
        ga, gwo, bo, out, nullptr, MROWS, VOCAB, DIMS);

    // join is complete (stream 0 waited on sW's last event); release handles
    cudaEventDestroy(evFork);
    cudaEventDestroy(evWv);
    cudaEventDestroy(evWo);
    cudaStreamDestroy(sW);
}

// round 13
// speedup vs baseline: 1.0013x; 1.0013x over previous
#include <cuda_runtime.h>
#include <cuda_fp16.h>
#include <cstdint>

// ---------------------------------------------------------------------------
// Problem constants
// ---------------------------------------------------------------------------
static constexpr int VOCAB = 32000;
static constexpr int DIMS  = 1024;
static constexpr int BB    = 2;
static constexpr int LL    = 2048;
static constexpr int MROWS = BB * LL;          // 4096
static constexpr int SEGS  = 128;              // cummean scan segments
static constexpr int SEGL  = LL / SEGS;        // 16
static constexpr int DCH   = 4;                // dim chunks per (b,seg) scan block

// Scratch (static device globals: allocation-free)
// cummean commutes with the W_V projection (both linear): scan first, then GEMMs.
__device__ __half g_eavg[MROWS * DIMS];        // fp16 cummean(e)   (A of GEMM1)
__device__ __half g_avg [MROWS * DIMS];        // fp16 avg = cummean(e)@W_V^T (A of GEMM2)
__device__ __half g_wv  [DIMS * DIMS];         // fp16 W_V
__device__ __half g_wo  [VOCAB * DIMS];        // fp16 W_out
__device__ float  g_seg [BB * SEGS * DIMS];    // segment sums for scan
__device__ int    g_is64;

// ---------------------------------------------------------------------------
// PTX helpers (base sm_100-compatible: cp.async + ldmatrix + mma.sync fp16)
// ---------------------------------------------------------------------------
__device__ __forceinline__ uint32_t smem_u32(const void* p) {
    uint32_t a;
    asm("{ .reg .u64 t; cvta.to.shared.u64 t, %1; cvt.u32.u64 %0, t; }" : "=r"(a) : "l"(p));
    return a;
}

#define CP_ASYNC16(dst, src) \
    asm volatile("cp.async.cg.shared.global [%0], [%1], 16;" :: "r"(dst), "l"(src) : "memory")
#define CP_COMMIT() asm volatile("cp.async.commit_group;" ::: "memory")
#define CP_WAIT1()  asm volatile("cp.async.wait_group 1;" ::: "memory")

__device__ __forceinline__ void ldsm_x4(uint32_t* r, uint32_t addr) {
    asm volatile("ldmatrix.sync.aligned.m8n8.x4.shared.b16 {%0,%1,%2,%3}, [%4];"
                 : "=r"(r[0]), "=r"(r[1]), "=r"(r[2]), "=r"(r[3]) : "r"(addr));
}

// fp16 MMA, fp32 accumulate: D[16,8] += A[16,16] * B[16,8] (B col-major = N,K row)
__device__ __forceinline__ void mma_f16(float* c, const uint32_t* a,
                                        uint32_t b0, uint32_t b1) {
    asm volatile(
        "mma.sync.aligned.m16n8k16.row.col.f32.f16.f16.f32 "
        "{%0,%1,%2,%3}, {%4,%5,%6,%7}, {%8,%9}, {%0,%1,%2,%3};"
        : "+f"(c[0]), "+f"(c[1]), "+f"(c[2]), "+f"(c[3])
        : "r"(a[0]), "r"(a[1]), "r"(a[2]), "r"(a[3]), "r"(b0), "r"(b1));
}

// ---------------------------------------------------------------------------
// GEMM: C[M,N] = A[M,K] * B[N,K]^T (+bias), fp16 mma.sync, fp32 accumulate.
// CTA tile 128(M) x 128(N) x 64(K); 4 warps (2x2) of 64x64; 3-stage cp.async.
// TWO CTAs per SM; grid x->M so co-resident CTAs share the B slice (L2-hot).
// Output dtype chosen at COMPILE time (OUT_HALF template).
// ---------------------------------------------------------------------------
static constexpr int MT = 128;
static constexpr int NT = 128;
static constexpr int KC = 64;                      // halves of K per chunk (128B/row)
static constexpr int STAGES = 3;
static constexpr int THREADS = 128;
static constexpr int ROWB = 144;                   // padded row stride in bytes
static constexpr int A_BYTES = MT * ROWB;          // 18432
static constexpr int B_BYTES = NT * ROWB;          // 18432
static constexpr int BUF     = A_BYTES + B_BYTES;  // 36864
static constexpr int SMEM_TOTAL = STAGES * BUF;    // 110592 (x2 CTAs = 221184 < 227KB)

__device__ __forceinline__ void load_chunk(uint32_t bufb,
                                           const __half* __restrict__ A,
                                           const __half* __restrict__ Bm,
                                           int mbase, int nbase, int K, int kc, int tid) {
    const int kofs = kc * KC;
#pragma unroll
    for (int i = 0; i < 8; i++) {                  // A: 128 rows x 8 segs / 128 thr
        int j = tid + (i << 7);
        int r = j >> 3, s = j & 7;
        const __half* src = A + (size_t)(mbase + r) * K + kofs + s * 8;
        CP_ASYNC16(bufb + (uint32_t)(r * ROWB + s * 16), src);
    }
#pragma unroll
    for (int i = 0; i < 8; i++) {                  // B: 128 rows x 8 segs / 128 thr
        int j = tid + (i << 7);
        int r = j >> 3, s = j & 7;
        const __half* src = Bm + (size_t)(nbase + r) * K + kofs + s * 8;
        CP_ASYNC16(bufb + (uint32_t)A_BYTES + (uint32_t)(r * ROWB + s * 16), src);
    }
}

// load fragments for one k16 step (4 A tiles m16k16, 4 B tiles n16k16)
__device__ __forceinline__ void load_frags(uint32_t bufb, uint32_t a_lane, uint32_t b_lane,
                                           int ks, uint32_t a[4][4], uint32_t b[4][4]) {
    const uint32_t boff = (uint32_t)(ks * 32);     // 16 halves = 32B per k16 step
#pragma unroll
    for (int mt = 0; mt < 4; mt++)
        ldsm_x4(a[mt], bufb + a_lane + (uint32_t)(mt * 16 * ROWB) + boff);
#pragma unroll
    for (int np = 0; np < 4; np++)
        ldsm_x4(b[np], bufb + b_lane + (uint32_t)(np * 16 * ROWB) + boff);
}

template <bool OUT_HALF>
__global__ void __launch_bounds__(THREADS, 2)
gemm_f16_mma(const __half* __restrict__ A, const __half* __restrict__ Bm,
             const float* __restrict__ bias, float* __restrict__ C,
             __half* __restrict__ Ch, int M, int N, int K) {
    extern __shared__ __align__(16) char smem[];
    const uint32_t sb = smem_u32(smem);
    const int tid = threadIdx.x;
    const int wid = tid >> 5;
    const int l   = tid & 31;
    const int wm  = wid >> 1;          // 0..1  (M warp row, 64 rows each)
    const int wn  = wid & 1;           // 0..1  (N warp col, 64 cols each)
    const int mbase = blockIdx.x * MT; // bx -> M: co-resident CTAs share B slice
    const int nbase = blockIdx.y * NT;

    const int      lrow = (l & 7) + ((l >> 3) & 1) * 8;
    const uint32_t lhi  = (uint32_t)((l >> 4) * 16);
    const uint32_t a_lane = (uint32_t)((wm * 64 + lrow) * ROWB) + lhi;
    const uint32_t b_lane = (uint32_t)A_BYTES + (uint32_t)((wn * 64 + lrow) * ROWB) + lhi;

    float c[4][8][4];
#pragma unroll
    for (int mt = 0; mt < 4; mt++)
#pragma unroll
        for (int nt = 0; nt < 8; nt++)
#pragma unroll
            for (int q = 0; q < 4; q++) c[mt][nt][q] = 0.0f;

    const int nch = K / KC;            // 16 for K=1024

    load_chunk(sb, A, Bm, mbase, nbase, K, 0, tid);
    CP_COMMIT();
    load_chunk(sb + BUF, A, Bm, mbase, nbase, K, 1, tid);
    CP_COMMIT();

    uint32_t afr[2][4][4], bfr[2][4][4];
    uint32_t slot = 0;
    for (int kc = 0; kc < nch; kc++) {
        CP_WAIT1();
        __syncthreads();
        const uint32_t bufb = sb + slot * BUF;
        if (kc + 2 < nch) {
            uint32_t ws = slot + 2; if (ws >= STAGES) ws -= STAGES;
            load_chunk(sb + ws * BUF, A, Bm, mbase, nbase, K, kc + 2, tid);
        }
        CP_COMMIT();

        load_frags(bufb, a_lane, b_lane, 0, afr[0], bfr[0]);
#pragma unroll
        for (int ks = 0; ks < 4; ks++) {           // 4 x k16 = K chunk of 64
            const int cur = ks & 1;
            if (ks < 3)
                load_frags(bufb, a_lane, b_lane, ks + 1, afr[cur ^ 1], bfr[cur ^ 1]);
#pragma unroll
            for (int mt = 0; mt < 4; mt++)
#pragma unroll
                for (int nt = 0; nt < 8; nt++) {
                    const int np = nt >> 1, od = nt & 1;
                    mma_f16(c[mt][nt], afr[cur][mt], bfr[cur][np][od], bfr[cur][np][2 + od]);
                }
        }
        slot++; if (slot >= STAGES) slot = 0;
    }

    // Epilogue: rows = mbase+wm*64+mt*16+{g,g+8}, cols = nbase+wn*64+nt*8+2t+{0,1}
    const int g = l >> 2, t = l & 3;
    const int row0 = mbase + wm * 64 + g;
    const int colb = nbase + wn * 64 + t * 2;
#pragma unroll
    for (int nt = 0; nt < 8; nt++) {
        float2 bv = make_float2(0.0f, 0.0f);
        if (bias) bv = *reinterpret_cast<const float2*>(bias + colb + nt * 8);
#pragma unroll
        for (int mt = 0; mt < 4; mt++) {
            const int r = row0 + mt * 16;
            float2 v0 = make_float2(c[mt][nt][0] + bv.x, c[mt][nt][1] + bv.y);
            float2 v1 = make_float2(c[mt][nt][2] + bv.x, c[mt][nt][3] + bv.y);
            if (OUT_HALF) {
                *reinterpret_cast<__half2*>(Ch + (size_t)r * N + colb + nt * 8)
                    = __floats2half2_rn(v0.x, v0.y);
                *reinterpret_cast<__half2*>(Ch + (size_t)(r + 8) * N + colb + nt * 8)
                    = __floats2half2_rn(v1.x, v1.y);
            } else {
                *reinterpret_cast<float2*>(C + (size_t)r * N + colb + nt * 8)       = v0;
                *reinterpret_cast<float2*>(C + (size_t)(r + 8) * N + colb + nt * 8) = v1;
            }
        }
    }
}

// ---------------------------------------------------------------------------
// Small kernels
// ---------------------------------------------------------------------------
__global__ void detect_kernel(const void* seq) {
    __shared__ int ok;
    if (threadIdx.x == 0) ok = 1;
    __syncthreads();
    const long long* p = (const long long*)seq;   // reads 16KB <= int32 buffer size
    for (int i = threadIdx.x; i < MROWS / 2; i += blockDim.x) {
        long long v = p[i];
        if (v < 0 || v >= VOCAB) ok = 0;
    }
    __syncthreads();
    if (threadIdx.x == 0) g_is64 = ok;
}

__device__ __forceinline__ long long get_tok(const void* seq, int idx) {
    if (g_is64) return ((const long long*)seq)[idx];
    return (long long)((const int*)seq)[idx];
}

// fp32 weights -> fp16 (round-to-nearest); 2 float4 per thread for MLP
__global__ void cvt_kernel(const float* __restrict__ src, __half* __restrict__ dst) {
    const size_t i0 = ((size_t)blockIdx.x * blockDim.x + threadIdx.x) * 2;
    float4 v0 = reinterpret_cast<const float4*>(src)[i0];
    float4 v1 = reinterpret_cast<const float4*>(src)[i0 + 1];
    __half2 h[4];
    h[0] = __floats2half2_rn(v0.x, v0.y);
    h[1] = __floats2half2_rn(v0.z, v0.w);
    h[2] = __floats2half2_rn(v1.x, v1.y);
    h[3] = __floats2half2_rn(v1.z, v1.w);
    reinterpret_cast<float4*>(dst)[i0 >> 1] = *reinterpret_cast<float4*>(h);
}

// --- fused gather + causal cumulative mean over EMBEDDINGS (scan-first) ----
// Scalar-float lanes, DCH=4 dim chunks: 1024 blocks x 256 thr (~86% occupancy)
// to hide gather latency. Consecutive threads read consecutive dims (coalesced).
// pass 1: per-(b,seg) sums of gathered embedding rows (fp32)
__global__ void segsum_emb(const void* __restrict__ seq, const float* __restrict__ emb,
                           float* __restrict__ S) {
    const int bs   = blockIdx.x >> 2;             // (b*SEGS+seg)
    const int b    = bs / SEGS;
    const int seg  = bs % SEGS;
    const int d    = (blockIdx.x & 3) * (DIMS / DCH) + threadIdx.x;
    const int lbase = b * LL + seg * SEGL;
    float acc = 0.0f;
#pragma unroll
    for (int lq = 0; lq < SEGL; lq++) {
        const long long tok = get_tok(seq, lbase + lq);
        acc += emb[(size_t)tok * DIMS + d];
    }
    S[(size_t)bs * DIMS + d] = acc;
}

// pass 2: prefix of segment sums (4-way MLP) + in-segment running mean -> fp16
__global__ void cummean_emb(const void* __restrict__ seq, const float* __restrict__ emb,
                            const float* __restrict__ S, __half* __restrict__ eavg) {
    const int bs   = blockIdx.x >> 2;
    const int b    = bs / SEGS;
    const int seg  = bs % SEGS;
    const int d    = (blockIdx.x & 3) * (DIMS / DCH) + threadIdx.x;
    float a0 = 0.f, a1 = 0.f, a2 = 0.f, a3 = 0.f;
    const float* Sp = S + (size_t)b * SEGS * DIMS + d;
    int j = 0;
    for (; j + 4 <= seg; j += 4) {
        a0 += Sp[(size_t)(j + 0) * DIMS];
        a1 += Sp[(size_t)(j + 1) * DIMS];
        a2 += Sp[(size_t)(j + 2) * DIMS];
        a3 += Sp[(size_t)(j + 3) * DIMS];
    }
    for (; j < seg; j++) a0 += Sp[(size_t)j * DIMS];
    float acc = (a0 + a1) + (a2 + a3);

    const int lbase = b * LL + seg * SEGL;
    __half* ap = eavg + (size_t)lbase * DIMS + d;
#pragma unroll
    for (int lq = 0; lq < SEGL; lq++) {
        const long long tok = get_tok(seq, lbase + lq);
        acc += emb[(size_t)tok * DIMS + d];
        const float inv = 1.0f / (float)(seg * SEGL + lq + 1);
        ap[(size_t)lq * DIMS] = __float2half_rn(acc * inv);
    }
}

// ---------------------------------------------------------------------------
// Launch (serial — fork/join measured neutral, reverted)
// ---------------------------------------------------------------------------
extern "C" void kernel_launch(void* const* d_in, const int* in_sizes, int n_in,
                              void* d_out, int out_size) {
    const void*  seq = d_in[0];
    const float* emb = (const float*)d_in[1];
    const float* WV  = (const float*)d_in[2];
    const float* WO  = (const float*)d_in[3];
    const float* bo  = (const float*)d_in[4];
    float* out = (float*)d_out;

    cudaFuncSetAttribute(gemm_f16_mma<false>,
                         cudaFuncAttributeMaxDynamicSharedMemorySize, SMEM_TOTAL);
    cudaFuncSetAttribute(gemm_f16_mma<true>,
                         cudaFuncAttributeMaxDynamicSharedMemorySize, SMEM_TOTAL);

    __half *gea, *ga, *gwv, *gwo;
    float *gs;
    cudaGetSymbolAddress((void**)&gea, g_eavg);
    cudaGetSymbolAddress((void**)&ga,  g_avg);
    cudaGetSymbolAddress((void**)&gwv, g_wv);
    cudaGetSymbolAddress((void**)&gwo, g_wo);
    cudaGetSymbolAddress((void**)&gs,  g_seg);

    detect_kernel<<<1, 256>>>(seq);
    cvt_kernel<<<(DIMS * DIMS) / 8 / 256, 256>>>(WV, gwv);
    cvt_kernel<<<(VOCAB * DIMS) / 8 / 256, 256>>>(WO, gwo);

    // scan-first: cummean(e) directly from gathered embeddings (1024-block grids)
    segsum_emb<<<BB * SEGS * DCH, 256>>>(seq, emb, gs);
    cummean_emb<<<BB * SEGS * DCH, 256>>>(seq, emb, gs, gea);

    // GEMM1: avg = cummean(e) @ W_V^T   [4096 x 1024 x 1024], fp16 output
    gemm_f16_mma<true><<<dim3(MROWS / MT, DIMS / NT), THREADS, SMEM_TOTAL>>>(
        gea, gwv, nullptr, nullptr, ga, MROWS, DIMS, DIMS);

    // GEMM2: out = avg @ W_out^T + b   [4096 x 32000 x 1024], fp32 output
    gemm_f16_mma<false><<<dim3(MROWS / MT, VOCAB / NT), THREADS, SMEM_TOTAL>>>(
        ga, gwo, bo, out, nullptr, MROWS, VOCAB, DIMS);
}

// round 14
// speedup vs baseline: 1.0043x; 1.0030x over previous
#include <cuda_runtime.h>
#include <cuda_fp16.h>
#include <cstdint>

// ---------------------------------------------------------------------------
// Problem constants
// ---------------------------------------------------------------------------
static constexpr int VOCAB = 32000;
static constexpr int DIMS  = 1024;
static constexpr int BB    = 2;
static constexpr int LL    = 2048;
static constexpr int MROWS = BB * LL;          // 4096
static constexpr int SEGS  = 128;              // cummean scan segments
static constexpr int SEGL  = LL / SEGS;        // 16
static constexpr int DCH   = 4;                // dim chunks per (b,seg) scan block

// Scratch (static device globals: allocation-free)
// cummean commutes with the W_V projection (both linear): scan first, then GEMMs.
__device__ __half g_eavg[MROWS * DIMS];        // fp16 cummean(e)   (A of GEMM1)
__device__ __half g_avg [MROWS * DIMS];        // fp16 avg = cummean(e)@W_V^T (A of GEMM2)
__device__ __half g_wv  [DIMS * DIMS];         // fp16 W_V
__device__ __half g_wo  [VOCAB * DIMS];        // fp16 W_out
__device__ float  g_seg [BB * SEGS * DIMS];    // segment sums for scan
__device__ int    g_is64;

// ---------------------------------------------------------------------------
// PTX helpers (base sm_100-compatible: cp.async + ldmatrix + mma.sync fp16)
// ---------------------------------------------------------------------------
__device__ __forceinline__ uint32_t smem_u32(const void* p) {
    uint32_t a;
    asm("{ .reg .u64 t; cvta.to.shared.u64 t, %1; cvt.u32.u64 %0, t; }" : "=r"(a) : "l"(p));
    return a;
}

#define CP_ASYNC16(dst, src) \
    asm volatile("cp.async.cg.shared.global [%0], [%1], 16;" :: "r"(dst), "l"(src) : "memory")
#define CP_COMMIT() asm volatile("cp.async.commit_group;" ::: "memory")
#define CP_WAIT1()  asm volatile("cp.async.wait_group 1;" ::: "memory")

__device__ __forceinline__ void ldsm_x4(uint32_t* r, uint32_t addr) {
    asm volatile("ldmatrix.sync.aligned.m8n8.x4.shared.b16 {%0,%1,%2,%3}, [%4];"
                 : "=r"(r[0]), "=r"(r[1]), "=r"(r[2]), "=r"(r[3]) : "r"(addr));
}

// fp16 MMA, fp32 accumulate: D[16,8] += A[16,16] * B[16,8] (B col-major = N,K row)
__device__ __forceinline__ void mma_f16(float* c, const uint32_t* a,
                                        uint32_t b0, uint32_t b1) {
    asm volatile(
        "mma.sync.aligned.m16n8k16.row.col.f32.f16.f16.f32 "
        "{%0,%1,%2,%3}, {%4,%5,%6,%7}, {%8,%9}, {%0,%1,%2,%3};"
        : "+f"(c[0]), "+f"(c[1]), "+f"(c[2]), "+f"(c[3])
        : "r"(a[0]), "r"(a[1]), "r"(a[2]), "r"(a[3]), "r"(b0), "r"(b1));
}

// ---------------------------------------------------------------------------
// GEMM: C[M,N] = A[M,K] * B[N,K]^T (+bias), fp16 mma.sync, fp32 accumulate.
// CTA tile 128(M) x 128(N) x 64(K); 4 warps (2x2) of 64x64; 3-stage cp.async.
// TWO CTAs per SM; grid x->M so co-resident CTAs share the B slice (L2-hot).
// Output dtype chosen at COMPILE time (OUT_HALF template).
// Measured at the legacy-HMMA structural ceiling (~512 MAC/cyc/SM).
// ---------------------------------------------------------------------------
static constexpr int MT = 128;
static constexpr int NT = 128;
static constexpr int KC = 64;                      // halves of K per chunk (128B/row)
static constexpr int STAGES = 3;
static constexpr int THREADS = 128;
static constexpr int ROWB = 144;                   // padded row stride in bytes
static constexpr int A_BYTES = MT * ROWB;          // 18432
static constexpr int B_BYTES = NT * ROWB;          // 18432
static constexpr int BUF     = A_BYTES + B_BYTES;  // 36864
static constexpr int SMEM_TOTAL = STAGES * BUF;    // 110592 (x2 CTAs = 221184 < 227KB)

__device__ __forceinline__ void load_chunk(uint32_t bufb,
                                           const __half* __restrict__ A,
                                           const __half* __restrict__ Bm,
                                           int mbase, int nbase, int K, int kc, int tid) {
    const int kofs = kc * KC;
#pragma unroll
    for (int i = 0; i < 8; i++) {                  // A: 128 rows x 8 segs / 128 thr
        int j = tid + (i << 7);
        int r = j >> 3, s = j & 7;
        const __half* src = A + (size_t)(mbase + r) * K + kofs + s * 8;
        CP_ASYNC16(bufb + (uint32_t)(r * ROWB + s * 16), src);
    }
#pragma unroll
    for (int i = 0; i < 8; i++) {                  // B: 128 rows x 8 segs / 128 thr
        int j = tid + (i << 7);
        int r = j >> 3, s = j & 7;
        const __half* src = Bm + (size_t)(nbase + r) * K + kofs + s * 8;
        CP_ASYNC16(bufb + (uint32_t)A_BYTES + (uint32_t)(r * ROWB + s * 16), src);
    }
}

// load fragments for one k16 step (4 A tiles m16k16, 4 B tiles n16k16)
__device__ __forceinline__ void load_frags(uint32_t bufb, uint32_t a_lane, uint32_t b_lane,
                                           int ks, uint32_t a[4][4], uint32_t b[4][4]) {
    const uint32_t boff = (uint32_t)(ks * 32);     // 16 halves = 32B per k16 step
#pragma unroll
    for (int mt = 0; mt < 4; mt++)
        ldsm_x4(a[mt], bufb + a_lane + (uint32_t)(mt * 16 * ROWB) + boff);
#pragma unroll
    for (int np = 0; np < 4; np++)
        ldsm_x4(b[np], bufb + b_lane + (uint32_t)(np * 16 * ROWB) + boff);
}

template <bool OUT_HALF>
__global__ void __launch_bounds__(THREADS, 2)
gemm_f16_mma(const __half* __restrict__ A, const __half* __restrict__ Bm,
             const float* __restrict__ bias, float* __restrict__ C,
             __half* __restrict__ Ch, int M, int N, int K) {
    extern __shared__ __align__(16) char smem[];
    const uint32_t sb = smem_u32(smem);
    const int tid = threadIdx.x;
    const int wid = tid >> 5;
    const int l   = tid & 31;
    const int wm  = wid >> 1;          // 0..1  (M warp row, 64 rows each)
    const int wn  = wid & 1;           // 0..1  (N warp col, 64 cols each)
    const int mbase = blockIdx.x * MT; // bx -> M: co-resident CTAs share B slice
    const int nbase = blockIdx.y * NT;

    const int      lrow = (l & 7) + ((l >> 3) & 1) * 8;
    const uint32_t lhi  = (uint32_t)((l >> 4) * 16);
    const uint32_t a_lane = (uint32_t)((wm * 64 + lrow) * ROWB) + lhi;
    const uint32_t b_lane = (uint32_t)A_BYTES + (uint32_t)((wn * 64 + lrow) * ROWB) + lhi;

    float c[4][8][4];
#pragma unroll
    for (int mt = 0; mt < 4; mt++)
#pragma unroll
        for (int nt = 0; nt < 8; nt++)
#pragma unroll
            for (int q = 0; q < 4; q++) c[mt][nt][q] = 0.0f;

    const int nch = K / KC;            // 16 for K=1024

    load_chunk(sb, A, Bm, mbase, nbase, K, 0, tid);
    CP_COMMIT();
    load_chunk(sb + BUF, A, Bm, mbase, nbase, K, 1, tid);
    CP_COMMIT();

    uint32_t afr[2][4][4], bfr[2][4][4];
    uint32_t slot = 0;
    for (int kc = 0; kc < nch; kc++) {
        CP_WAIT1();
        __syncthreads();
        const uint32_t bufb = sb + slot * BUF;
        if (kc + 2 < nch) {
            uint32_t ws = slot + 2; if (ws >= STAGES) ws -= STAGES;
            load_chunk(sb + ws * BUF, A, Bm, mbase, nbase, K, kc + 2, tid);
        }
        CP_COMMIT();

        load_frags(bufb, a_lane, b_lane, 0, afr[0], bfr[0]);
#pragma unroll
        for (int ks = 0; ks < 4; ks++) {           // 4 x k16 = K chunk of 64
            const int cur = ks & 1;
            if (ks < 3)
                load_frags(bufb, a_lane, b_lane, ks + 1, afr[cur ^ 1], bfr[cur ^ 1]);
#pragma unroll
            for (int mt = 0; mt < 4; mt++)
#pragma unroll
                for (int nt = 0; nt < 8; nt++) {
                    const int np = nt >> 1, od = nt & 1;
                    mma_f16(c[mt][nt], afr[cur][mt], bfr[cur][np][od], bfr[cur][np][2 + od]);
                }
        }
        slot++; if (slot >= STAGES) slot = 0;
    }

    // Epilogue: rows = mbase+wm*64+mt*16+{g,g+8}, cols = nbase+wn*64+nt*8+2t+{0,1}
    const int g = l >> 2, t = l & 3;
    const int row0 = mbase + wm * 64 + g;
    const int colb = nbase + wn * 64 + t * 2;
#pragma unroll
    for (int nt = 0; nt < 8; nt++) {
        float2 bv = make_float2(0.0f, 0.0f);
        if (bias) bv = *reinterpret_cast<const float2*>(bias + colb + nt * 8);
#pragma unroll
        for (int mt = 0; mt < 4; mt++) {
            const int r = row0 + mt * 16;
            float2 v0 = make_float2(c[mt][nt][0] + bv.x, c[mt][nt][1] + bv.y);
            float2 v1 = make_float2(c[mt][nt][2] + bv.x, c[mt][nt][3] + bv.y);
            if (OUT_HALF) {
                *reinterpret_cast<__half2*>(Ch + (size_t)r * N + colb + nt * 8)
                    = __floats2half2_rn(v0.x, v0.y);
                *reinterpret_cast<__half2*>(Ch + (size_t)(r + 8) * N + colb + nt * 8)
                    = __floats2half2_rn(v1.x, v1.y);
            } else {
                *reinterpret_cast<float2*>(C + (size_t)r * N + colb + nt * 8)       = v0;
                *reinterpret_cast<float2*>(C + (size_t)(r + 8) * N + colb + nt * 8) = v1;
            }
        }
    }
}

// ---------------------------------------------------------------------------
// Small kernels
// ---------------------------------------------------------------------------
__global__ void detect_kernel(const void* seq) {
    __shared__ int ok;
    if (threadIdx.x == 0) ok = 1;
    __syncthreads();
    const long long* p = (const long long*)seq;   // reads 16KB <= int32 buffer size
    for (int i = threadIdx.x; i < MROWS / 2; i += blockDim.x) {
        long long v = p[i];
        if (v < 0 || v >= VOCAB) ok = 0;
    }
    __syncthreads();
    if (threadIdx.x == 0) g_is64 = ok;
}

__device__ __forceinline__ long long get_tok(const void* seq, int idx) {
    if (g_is64) return ((const long long*)seq)[idx];
    return (long long)((const int*)seq)[idx];
}

// Both weight tensors fp32 -> fp16 in ONE launch (saves a launch + drain).
// Blocks [0, nWv) convert W_V; blocks [nWv, nWv+nWo) convert W_out.
// 2 float4 per thread for MLP; at HBM roofline.
__global__ void cvt_dual_kernel(const float* __restrict__ wv_src, __half* __restrict__ wv_dst,
                                const float* __restrict__ wo_src, __half* __restrict__ wo_dst,
                                int nWv) {
    const float* src; __half* dst; size_t base;
    if ((int)blockIdx.x < nWv) {
        src = wv_src; dst = wv_dst; base = (size_t)blockIdx.x;
    } else {
        src = wo_src; dst = wo_dst; base = (size_t)(blockIdx.x - nWv);
    }
    const size_t i0 = (base * blockDim.x + threadIdx.x) * 2;
    float4 v0 = reinterpret_cast<const float4*>(src)[i0];
    float4 v1 = reinterpret_cast<const float4*>(src)[i0 + 1];
    __half2 h[4];
    h[0] = __floats2half2_rn(v0.x, v0.y);
    h[1] = __floats2half2_rn(v0.z, v0.w);
    h[2] = __floats2half2_rn(v1.x, v1.y);
    h[3] = __floats2half2_rn(v1.z, v1.w);
    reinterpret_cast<float4*>(dst)[i0 >> 1] = *reinterpret_cast<float4*>(h);
}

// --- fused gather + causal cumulative mean over EMBEDDINGS (scan-first) ----
// Scalar-float lanes, DCH=4 dim chunks: 1024 blocks x 256 thr.
// pass 1: per-(b,seg) sums of gathered embedding rows (fp32)
__global__ void segsum_emb(const void* __restrict__ seq, const float* __restrict__ emb,
                           float* __restrict__ S) {
    const int bs   = blockIdx.x >> 2;             // (b*SEGS+seg)
    const int b    = bs / SEGS;
    const int seg  = bs % SEGS;
    const int d    = (blockIdx.x & 3) * (DIMS / DCH) + threadIdx.x;
    const int lbase = b * LL + seg * SEGL;
    float acc = 0.0f;
#pragma unroll
    for (int lq = 0; lq < SEGL; lq++) {
        const long long tok = get_tok(seq, lbase + lq);
        acc += emb[(size_t)tok * DIMS + d];
    }
    S[(size_t)bs * DIMS + d] = acc;
}

// pass 2: prefix of segment sums (4-way MLP) + in-segment running mean -> fp16
__global__ void cummean_emb(const void* __restrict__ seq, const float* __restrict__ emb,
                            const float* __restrict__ S, __half* __restrict__ eavg) {
    const int bs   = blockIdx.x >> 2;
    const int b    = bs / SEGS;
    const int seg  = bs % SEGS;
    const int d    = (blockIdx.x & 3) * (DIMS / DCH) + threadIdx.x;
    float a0 = 0.f, a1 = 0.f, a2 = 0.f, a3 = 0.f;
    const float* Sp = S + (size_t)b * SEGS * DIMS + d;
    int j = 0;
    for (; j + 4 <= seg; j += 4) {
        a0 += Sp[(size_t)(j + 0) * DIMS];
        a1 += Sp[(size_t)(j + 1) * DIMS];
        a2 += Sp[(size_t)(j + 2) * DIMS];
        a3 += Sp[(size_t)(j + 3) * DIMS];
    }
    for (; j < seg; j++) a0 += Sp[(size_t)j * DIMS];
    float acc = (a0 + a1) + (a2 + a3);

    const int lbase = b * LL + seg * SEGL;
    __half* ap = eavg + (size_t)lbase * DIMS + d;
#pragma unroll
    for (int lq = 0; lq < SEGL; lq++) {
        const long long tok = get_tok(seq, lbase + lq);
        acc += emb[(size_t)tok * DIMS + d];
        const float inv = 1.0f / (float)(seg * SEGL + lq + 1);
        ap[(size_t)lq * DIMS] = __float2half_rn(acc * inv);
    }
}

// ---------------------------------------------------------------------------
// Launch (serial; fork/join measured neutral in R12 and reverted)
// ---------------------------------------------------------------------------
extern "C" void kernel_launch(void* const* d_in, const int* in_sizes, int n_in,
                              void* d_out, int out_size) {
    const void*  seq = d_in[0];
    const float* emb = (const float*)d_in[1];
    const float* WV  = (const float*)d_in[2];
    const float* WO  = (const float*)d_in[3];
    const float* bo  = (const float*)d_in[4];
    float* out = (float*)d_out;

    cudaFuncSetAttribute(gemm_f16_mma<false>,
                         cudaFuncAttributeMaxDynamicSharedMemorySize, SMEM_TOTAL);
    cudaFuncSetAttribute(gemm_f16_mma<true>,
                         cudaFuncAttributeMaxDynamicSharedMemorySize, SMEM_TOTAL);

    __half *gea, *ga, *gwv, *gwo;
    float *gs;
    cudaGetSymbolAddress((void**)&gea, g_eavg);
    cudaGetSymbolAddress((void**)&ga,  g_avg);
    cudaGetSymbolAddress((void**)&gwv, g_wv);
    cudaGetSymbolAddress((void**)&gwo, g_wo);
    cudaGetSymbolAddress((void**)&gs,  g_seg);

    constexpr int nWv = (DIMS * DIMS)  / 8 / 256;   // 512 blocks
    constexpr int nWo = (VOCAB * DIMS) / 8 / 256;   // 16000 blocks

    detect_kernel<<<1, 256>>>(seq);
    cvt_dual_kernel<<<nWv + nWo, 256>>>(WV, gwv, WO, gwo, nWv);

    // scan-first: cummean(e) directly from gathered embeddings (1024-block grids)
    segsum_emb<<<BB * SEGS * DCH, 256>>>(seq, emb, gs);
    cummean_emb<<<BB * SEGS * DCH, 256>>>(seq, emb, gs, gea);

    // GEMM1: avg = cummean(e) @ W_V^T   [4096 x 1024 x 1024], fp16 output
    gemm_f16_mma<true><<<dim3(MROWS / MT, DIMS / NT), THREADS, SMEM_TOTAL>>>(
        gea, gwv, nullptr, nullptr, ga, MROWS, DIMS, DIMS);

    // GEMM2: out = avg @ W_out^T + b   [4096 x 32000 x 1024], fp32 output
    gemm_f16_mma<false><<<dim3(MROWS / MT, VOCAB / NT), THREADS, SMEM_TOTAL>>>(
        ga, gwo, bo, out, nullptr, MROWS, VOCAB, DIMS);
}